// round 3
// baseline (speedup 1.0000x reference)
#include <cuda_runtime.h>
#include <math.h>

// Problem constants
static constexpr int IW = 1024;
static constexpr int IH = 1024;
static constexpr int NB = 16;
static constexpr int IMG = IW * IH;           // 1<<20
static constexpr int TOTAL = NB * IMG;        // 16M
static constexpr int NPASS = 16;

// Scratch (device globals: allocation-free rule)
__device__ float         g_blur[TOTAL];        // 64MB
__device__ float         g_thin[TOTAL];        // 64MB (unnormalized thin magnitudes)
__device__ unsigned char g_state[TOTAL];       // 16MB: 0=none 1=weak 2=strong
__device__ unsigned int  g_magmax[NB];         // per-batch max(mag), float bits
__device__ unsigned int  g_thinmax[NB];        // per-batch max(thin_unnorm), float bits
__device__ float         g_hi;                 // global strong threshold (normalized)
__device__ int           g_flags[NPASS];       // hysteresis per-pass "changed" flags

// ---------------------------------------------------------------- reset
__global__ void k_reset() {
    int t = threadIdx.x;
    if (t < NB) { g_magmax[t] = 0u; g_thinmax[t] = 0u; }
    if (t < NPASS) g_flags[t] = 0;
}

// ---------------------------------------------------------------- gaussian blur (separable, fused)
__global__ void __launch_bounds__(256) k_blur(const float* __restrict__ img) {
    __shared__ float si[36][36];
    __shared__ float hb[36][33];
    const int b  = blockIdx.z;
    const int x0 = blockIdx.x * 32, y0 = blockIdx.y * 32;
    const float* im = img + (size_t)b * IMG;
    const int tid = threadIdx.x;

    for (int i = tid; i < 36 * 36; i += 256) {
        int r = i / 36, c = i % 36;
        int gy = y0 + r - 2, gx = x0 + c - 2;
        float v = 0.f;
        if ((unsigned)gy < (unsigned)IH && (unsigned)gx < (unsigned)IW) v = im[gy * IW + gx];
        si[r][c] = v;
    }
    __syncthreads();

    // unnormalized gaussian window, sigma=1, K=5 (matches np.exp values)
    const float G0 = 0.13533528323661270231f;  // exp(-2)
    const float G1 = 0.60653065971263342360f;  // exp(-0.5)
    const int c  = tid & 31;
    const int r0 = tid >> 5;

    for (int r = r0; r < 36; r += 8) {
        float v = G0 * si[r][c];
        v += G1 * si[r][c + 1];
        v += si[r][c + 2];
        v += G1 * si[r][c + 3];
        v += G0 * si[r][c + 4];
        hb[r][c] = v;
    }
    __syncthreads();

    float* ob = g_blur + (size_t)b * IMG;
    for (int r = r0; r < 32; r += 8) {
        float v = G0 * hb[r][c];
        v += G1 * hb[r + 1][c];
        v += hb[r + 2][c];
        v += G1 * hb[r + 3][c];
        v += G0 * hb[r + 4][c];
        ob[(y0 + r) * IW + x0 + c] = v;
    }
}

// ---------------------------------------------------------------- sobel + mag + NMS + per-batch maxima
__global__ void __launch_bounds__(256) k_grad() {
    __shared__ float sb[36][36];   // blurred with halo 2
    __shared__ float sm[34][34];   // mag with halo 1 (0 outside image, matching zero-pad conv of mag)
    __shared__ float red[16];
    const int b  = blockIdx.z;
    const int x0 = blockIdx.x * 32, y0 = blockIdx.y * 32;
    const float* bl = g_blur + (size_t)b * IMG;
    const int tid = threadIdx.x;

    for (int i = tid; i < 36 * 36; i += 256) {
        int r = i / 36, c = i % 36;
        int gy = y0 + r - 2, gx = x0 + c - 2;
        float v = 0.f;
        if ((unsigned)gy < (unsigned)IH && (unsigned)gx < (unsigned)IW) v = bl[gy * IW + gx];
        sb[r][c] = v;
    }
    __syncthreads();

    for (int i = tid; i < 34 * 34; i += 256) {
        int r = i / 34, c = i % 34;
        int gy = y0 + r - 1, gx = x0 + c - 1;
        float m = 0.f;
        if ((unsigned)gy < (unsigned)IH && (unsigned)gx < (unsigned)IW) {
            float a0 = sb[r][c],     a1 = sb[r][c + 1],     a2 = sb[r][c + 2];
            float b0 = sb[r + 1][c],                        b2 = sb[r + 1][c + 2];
            float c0 = sb[r + 2][c], c1 = sb[r + 2][c + 1], c2 = sb[r + 2][c + 2];
            float Ix = (a0 - a2) + 2.f * (b0 - b2) + (c0 - c2);
            float Iy = (a0 - c0) + 2.f * (a1 - c1) + (a2 - c2);
            m = sqrtf(Ix * Ix + Iy * Iy);
        }
        sm[r][c] = m;
    }
    __syncthreads();

    const int cx = tid & 31;
    const int r0 = tid >> 5;
    const float KC = (float)(180.0 / 3.1415926);
    float mmax = 0.f, tmax = 0.f;
    float* tp = g_thin + (size_t)b * IMG;

    for (int ry = r0; ry < 32; ry += 8) {
        const int r = ry + 1, c = cx + 1;   // sm coords of this pixel
        float m = sm[r][c];
        // recompute gradient at this pixel (sb window = sm coords shifted by +0..+2)
        float a0 = sb[r][c],     a1 = sb[r][c + 1],     a2 = sb[r][c + 2];
        float b0 = sb[r + 1][c],                        b2 = sb[r + 1][c + 2];
        float c0 = sb[r + 2][c], c1 = sb[r + 2][c + 1], c2 = sb[r + 2][c + 2];
        float Ix = (a0 - a2) + 2.f * (b0 - b2) + (c0 - c2);
        float Iy = (a0 - c0) + 2.f * (a1 - c1) + (a2 - c2);
        float d = atan2f(Iy, Ix) * KC + 180.0f;
        int q = (int)rintf(d / 45.0f);   // round-half-even, matches jnp.round
        int idx = q & 7;
        // idx -> neighbor offset (dy,dx): 0:(0,1) 1:(1,1) 2:(1,0) 3:(1,-1) 4:(0,-1) 5:(-1,-1) 6:(-1,0) 7:(-1,1)
        int dy = (int)((0x00012221u >> (4 * idx)) & 0xFu) - 1;
        int dx = (int)((0x21000122u >> (4 * idx)) & 0xFu) - 1;
        float n1 = sm[r + dy][c + dx];
        float n2 = sm[r - dy][c - dx];
        float thin = (m > n1 && m > n2) ? m : 0.f;   // min(m-n1, m-n2) > 0
        tp[(y0 + ry) * IW + x0 + cx] = thin;
        mmax = fmaxf(mmax, m);
        tmax = fmaxf(tmax, thin);
    }

    for (int o = 16; o; o >>= 1) {
        mmax = fmaxf(mmax, __shfl_xor_sync(0xffffffffu, mmax, o));
        tmax = fmaxf(tmax, __shfl_xor_sync(0xffffffffu, tmax, o));
    }
    int warp = tid >> 5, lane = tid & 31;
    if (lane == 0) { red[warp] = mmax; red[warp + 8] = tmax; }
    __syncthreads();
    if (tid == 0) {
        float a = red[0], t2 = red[8];
        for (int w = 1; w < 8; w++) { a = fmaxf(a, red[w]); t2 = fmaxf(t2, red[w + 8]); }
        atomicMax(&g_magmax[b], __float_as_uint(a));
        atomicMax(&g_thinmax[b], __float_as_uint(t2));
    }
}

// ---------------------------------------------------------------- global strong threshold
__global__ void k_hi() {
    int t = threadIdx.x;
    float v = 0.f;
    if (t < NB) {
        float M = __uint_as_float(g_magmax[t]);
        v = __uint_as_float(g_thinmax[t]) / M;   // exact IEEE div; monotone => max of divided = divided max
    }
    for (int o = 16; o; o >>= 1) v = fmaxf(v, __shfl_xor_sync(0xffffffffu, v, o));
    if (t == 0) g_hi = v * 0.15f;
}

// ---------------------------------------------------------------- classify (double threshold)
__global__ void __launch_bounds__(256) k_class() {
    int i = blockIdx.x * 256 + threadIdx.x;
    int b = i >> 20;
    float M = __uint_as_float(g_magmax[b]);
    float t = g_thin[i] / M;                    // exact division: bit-matches reference's normalized thin
    float hi = g_hi;
    unsigned char s = (t >= hi) ? (unsigned char)2
                    : ((t >= 0.00392f) ? (unsigned char)1 : (unsigned char)0);
    g_state[i] = s;
}

// ---------------------------------------------------------------- hysteresis pass (tile-local fixpoint)
__global__ void __launch_bounds__(256) k_hyst(int pass) {
    if (pass > 0 && g_flags[pass - 1] == 0) return;   // converged: cheap no-op pass

    __shared__ unsigned char s[66][68];
    __shared__ int s_changed;
    __shared__ int s_any;
    const int b  = blockIdx.z;
    const int x0 = blockIdx.x * 64, y0 = blockIdx.y * 64;
    unsigned char* st = g_state + (size_t)b * IMG;
    const int tid = threadIdx.x;

    if (tid == 0) s_any = 0;
    for (int i = tid; i < 66 * 66; i += 256) {
        int r = i / 66, c = i % 66;
        int gy = y0 + r - 1, gx = x0 + c - 1;
        unsigned char v = 0;
        if ((unsigned)gy < (unsigned)IH && (unsigned)gx < (unsigned)IW) v = st[gy * IW + gx];
        s[r][c] = v;
    }

    for (;;) {
        __syncthreads();                 // guards previous iteration's reads of s_changed
        if (tid == 0) s_changed = 0;
        __syncthreads();
        for (int p = tid; p < 4096; p += 256) {
            int r = (p >> 6) + 1, c = (p & 63) + 1;
            if (s[r][c] == 1) {
                int near = (s[r-1][c-1] == 2) | (s[r-1][c] == 2) | (s[r-1][c+1] == 2) |
                           (s[r  ][c-1] == 2) |                    (s[r  ][c+1] == 2) |
                           (s[r+1][c-1] == 2) | (s[r+1][c] == 2) | (s[r+1][c+1] == 2);
                if (near) { s[r][c] = 2; s_changed = 1; s_any = 1; }
            }
        }
        __syncthreads();
        if (!s_changed) break;
    }

    if (s_any) {
        for (int p = tid; p < 4096; p += 256) {
            int r = (p >> 6) + 1, c = (p & 63) + 1;
            st[(y0 + r - 1) * IW + (x0 + c - 1)] = s[r][c];
        }
        if (tid == 0) g_flags[pass] = 1;
    }
}

// ---------------------------------------------------------------- final write
__global__ void __launch_bounds__(256) k_final(float* __restrict__ out) {
    int i = blockIdx.x * 256 + threadIdx.x;
    out[i] = (g_state[i] == 2) ? 255.0f : 0.0f;
}

// ---------------------------------------------------------------- launch
extern "C" void kernel_launch(void* const* d_in, const int* in_sizes, int n_in,
                              void* d_out, int out_size) {
    (void)in_sizes; (void)n_in; (void)out_size;
    const float* img = (const float*)d_in[0];
    float* out = (float*)d_out;

    dim3 tg(32, 32, 16);       // 32x32 tiles
    dim3 hg(16, 16, 16);       // 64x64 tiles

    k_reset<<<1, 64>>>();
    k_blur<<<tg, 256>>>(img);
    k_grad<<<tg, 256>>>();
    k_hi<<<1, 32>>>();
    k_class<<<TOTAL / 256, 256>>>();
    for (int p = 0; p < NPASS; p++) k_hyst<<<hg, 256>>>(p);
    k_final<<<TOTAL / 256, 256>>>(out);
}

// round 4
// speedup vs baseline: 1.5211x; 1.5211x over previous
#include <cuda_runtime.h>
#include <math.h>

// Problem constants
static constexpr int IW = 1024;
static constexpr int IH = 1024;
static constexpr int NB = 16;
static constexpr int IMG = IW * IH;           // 1<<20
static constexpr int TOTAL = NB * IMG;        // 16M
static constexpr int NPASS = 16;
static constexpr int WPR = IW / 32;           // 32 words per row
static constexpr int WPI = IMG / 32;          // words per image

// Scratch (device globals: allocation-free rule)
__device__ float         g_thin[TOTAL];        // 64MB unnormalized thin magnitudes
__device__ unsigned int  g_sbits[TOTAL / 32];  // 2MB strong bitmap
__device__ unsigned int  g_wbits[TOTAL / 32];  // 2MB weak bitmap
__device__ unsigned int  g_magmax[NB];         // per-batch max(mag), float bits
__device__ unsigned int  g_thinmax[NB];        // per-batch max(thin), float bits
__device__ float         g_hi;                 // global strong threshold (normalized)
__device__ int           g_flags[NPASS];       // hysteresis per-pass "changed" flags

// ---------------------------------------------------------------- reset
__global__ void k_reset() {
    int t = threadIdx.x;
    if (t < NB) { g_magmax[t] = 0u; g_thinmax[t] = 0u; }
    if (t < NPASS) g_flags[t] = 0;
}

// ---------------------------------------------------------------- fused blur + sobel + NMS + per-batch maxima
__global__ void __launch_bounds__(256) k_main(const float* __restrict__ img) {
    __shared__ float si[40][40];   // raw img, halo 4
    __shared__ float hb[40][36];   // horizontal blur
    __shared__ float sb[36][36];   // blurred, halo 2 (0 outside image = conv padding)
    __shared__ float sm[34][34];   // mag, halo 1 (0 outside image)
    __shared__ float red[16];
    const int b  = blockIdx.z;
    const int x0 = blockIdx.x * 32, y0 = blockIdx.y * 32;
    const float* im = img + (size_t)b * IMG;
    const int tid = threadIdx.x;

    for (int i = tid; i < 40 * 40; i += 256) {
        int r = i / 40, c = i % 40;
        int gy = y0 + r - 4, gx = x0 + c - 4;
        float v = 0.f;
        if ((unsigned)gy < (unsigned)IH && (unsigned)gx < (unsigned)IW) v = im[gy * IW + gx];
        si[r][c] = v;
    }
    __syncthreads();

    // unnormalized gaussian window, sigma=1, K=5
    const float G0 = 0.13533528323661270231f;  // exp(-2)
    const float G1 = 0.60653065971263342360f;  // exp(-0.5)

    for (int i = tid; i < 40 * 36; i += 256) {
        int r = i / 36, c = i % 36;
        float v = G0 * si[r][c];
        v += G1 * si[r][c + 1];
        v += si[r][c + 2];
        v += G1 * si[r][c + 3];
        v += G0 * si[r][c + 4];
        hb[r][c] = v;
    }
    __syncthreads();

    for (int i = tid; i < 36 * 36; i += 256) {
        int r = i / 36, c = i % 36;
        int gy = y0 + r - 2, gx = x0 + c - 2;
        float v = 0.f;
        if ((unsigned)gy < (unsigned)IH && (unsigned)gx < (unsigned)IW) {
            v = G0 * hb[r][c];
            v += G1 * hb[r + 1][c];
            v += hb[r + 2][c];
            v += G1 * hb[r + 3][c];
            v += G0 * hb[r + 4][c];
        }
        sb[r][c] = v;
    }
    __syncthreads();

    for (int i = tid; i < 34 * 34; i += 256) {
        int r = i / 34, c = i % 34;
        int gy = y0 + r - 1, gx = x0 + c - 1;
        float m = 0.f;
        if ((unsigned)gy < (unsigned)IH && (unsigned)gx < (unsigned)IW) {
            float a0 = sb[r][c],     a1 = sb[r][c + 1],     a2 = sb[r][c + 2];
            float b0 = sb[r + 1][c],                        b2 = sb[r + 1][c + 2];
            float c0 = sb[r + 2][c], c1 = sb[r + 2][c + 1], c2 = sb[r + 2][c + 2];
            float Ix = (a0 - a2) + 2.f * (b0 - b2) + (c0 - c2);
            float Iy = (a0 - c0) + 2.f * (a1 - c1) + (a2 - c2);
            m = sqrtf(Ix * Ix + Iy * Iy);
        }
        sm[r][c] = m;
    }
    __syncthreads();

    const int cx = tid & 31;
    const int r0 = tid >> 5;
    const float T1 = 0.41421356237309503f;   // tan(22.5 deg)
    float mmax = 0.f, tmax = 0.f;
    float* tp = g_thin + (size_t)b * IMG;

    for (int ry = r0; ry < 32; ry += 8) {
        const int r = ry + 1, c = cx + 1;   // sm coords of this pixel
        float m = sm[r][c];
        // recompute gradient at this pixel (sb window offset matches sm coords)
        float a0 = sb[r][c],     a1 = sb[r][c + 1],     a2 = sb[r][c + 2];
        float b0 = sb[r + 1][c],                        b2 = sb[r + 1][c + 2];
        float c0 = sb[r + 2][c], c1 = sb[r + 2][c + 1], c2 = sb[r + 2][c + 2];
        float Ix = (a0 - a2) + 2.f * (b0 - b2) + (c0 - c2);
        float Iy = (a0 - c0) + 2.f * (a1 - c1) + (a2 - c2);
        // Quantized-direction axis without atan2: only idx mod 4 matters (NMS is
        // symmetric in idx / idx+4). Tie directions (<=) match round-half-even of
        // the reference: 22.5->axis0, 67.5->axis2, 112.5->axis2, 157.5->axis0.
        float ax = fabsf(Ix), ay = fabsf(Iy);
        int dy, dx;
        if (ay <= T1 * ax)      { dy = 0; dx = 1; }                       // E-W
        else if (ax <= T1 * ay) { dy = 1; dx = 0; }                       // N-S
        else if ((__float_as_int(Ix) ^ __float_as_int(Iy)) >= 0) { dy = 1; dx = 1; }  // 45 deg family
        else                    { dy = 1; dx = -1; }                      // 135 deg family
        float n1 = sm[r + dy][c + dx];
        float n2 = sm[r - dy][c - dx];
        float thin = (m > n1 && m > n2) ? m : 0.f;
        tp[(y0 + ry) * IW + x0 + cx] = thin;
        mmax = fmaxf(mmax, m);
        tmax = fmaxf(tmax, thin);
    }

    for (int o = 16; o; o >>= 1) {
        mmax = fmaxf(mmax, __shfl_xor_sync(0xffffffffu, mmax, o));
        tmax = fmaxf(tmax, __shfl_xor_sync(0xffffffffu, tmax, o));
    }
    int warp = tid >> 5, lane = tid & 31;
    if (lane == 0) { red[warp] = mmax; red[warp + 8] = tmax; }
    __syncthreads();
    if (tid == 0) {
        float a = red[0], t2 = red[8];
        for (int w = 1; w < 8; w++) { a = fmaxf(a, red[w]); t2 = fmaxf(t2, red[w + 8]); }
        atomicMax(&g_magmax[b], __float_as_uint(a));
        atomicMax(&g_thinmax[b], __float_as_uint(t2));
    }
}

// ---------------------------------------------------------------- global strong threshold
__global__ void k_hi() {
    int t = threadIdx.x;
    float v = 0.f;
    if (t < NB) {
        float M = __uint_as_float(g_magmax[t]);
        v = __uint_as_float(g_thinmax[t]) / M;   // monotone => max of divided = divided max
    }
    for (int o = 16; o; o >>= 1) v = fmaxf(v, __shfl_xor_sync(0xffffffffu, v, o));
    if (t == 0) g_hi = v * 0.15f;
}

// ---------------------------------------------------------------- classify -> bitmaps
__global__ void __launch_bounds__(256) k_class() {
    int i = blockIdx.x * 256 + threadIdx.x;
    int b = i >> 20;
    float M = __uint_as_float(g_magmax[b]);
    float t = g_thin[i] / M;                    // exact division: bit-matches reference
    float hi = g_hi;
    bool st = (t >= hi);
    bool wk = !st && (t >= 0.00392f);
    unsigned sbv = __ballot_sync(0xffffffffu, st);
    unsigned wbv = __ballot_sync(0xffffffffu, wk);
    if ((threadIdx.x & 31) == 0) { g_sbits[i >> 5] = sbv; g_wbits[i >> 5] = wbv; }
}

// ---------------------------------------------------------------- hysteresis pass on bitmaps
// Tile = 64 rows x full 1024-px width. Word-parallel 8-neighbor dilation to
// tile-local fixpoint; halos from neighbor tiles' previous-pass state.
__global__ void __launch_bounds__(256) k_hystb(int pass) {
    if (pass > 0 && g_flags[pass - 1] == 0) return;   // converged: cheap no-op pass

    __shared__ unsigned us[66][WPR];
    __shared__ unsigned uw[64][WPR];
    __shared__ int s_changed, s_any;
    const int y0 = blockIdx.x * 64;
    const int b  = blockIdx.y;
    const unsigned* S = g_sbits + b * WPI;
    const unsigned* W = g_wbits + b * WPI;
    const int tid = threadIdx.x;

    if (tid == 0) s_any = 0;
    for (int i = tid; i < 66 * WPR; i += 256) {
        int r = i >> 5, w = i & 31;
        int gy = y0 + r - 1;
        us[r][w] = ((unsigned)gy < (unsigned)IH) ? S[gy * WPR + w] : 0u;
    }
    for (int i = tid; i < 64 * WPR; i += 256) {
        int r = i >> 5, w = i & 31;
        uw[r][w] = W[(y0 + r) * WPR + w];
    }

    for (;;) {
        __syncthreads();
        if (tid == 0) s_changed = 0;
        __syncthreads();
        for (int p = tid; p < 64 * WPR; p += 256) {
            int r = p >> 5, w = p & 31;
            unsigned wk = uw[r][w];
            if (!wk) continue;
            unsigned cen = us[r + 1][w];
            wk &= ~cen;
            if (!wk) continue;
            unsigned up = us[r][w], dn = us[r + 2][w];
            unsigned pu = w ? us[r][w - 1] : 0u,      nu = (w < 31) ? us[r][w + 1] : 0u;
            unsigned pc = w ? us[r + 1][w - 1] : 0u,  nc = (w < 31) ? us[r + 1][w + 1] : 0u;
            unsigned pd = w ? us[r + 2][w - 1] : 0u,  nd = (w < 31) ? us[r + 2][w + 1] : 0u;
            unsigned nb = up | (up << 1) | (up >> 1) | (pu >> 31) | (nu << 31)
                        | dn | (dn << 1) | (dn >> 1) | (pd >> 31) | (nd << 31)
                        |      (cen << 1) | (cen >> 1) | (pc >> 31) | (nc << 31);
            unsigned ns = wk & nb;
            if (ns) { us[r + 1][w] = cen | ns; s_changed = 1; s_any = 1; }
        }
        __syncthreads();
        if (!s_changed) break;
    }

    if (s_any) {
        unsigned* So = g_sbits + b * WPI;
        for (int i = tid; i < 64 * WPR; i += 256) {
            int r = i >> 5, w = i & 31;
            So[(y0 + r) * WPR + w] = us[r + 1][w];
        }
        if (tid == 0) g_flags[pass] = 1;
    }
}

// ---------------------------------------------------------------- final write
__global__ void __launch_bounds__(256) k_final(float* __restrict__ out) {
    int i = blockIdx.x * 256 + threadIdx.x;
    out[i] = ((g_sbits[i >> 5] >> (i & 31)) & 1u) ? 255.0f : 0.0f;
}

// ---------------------------------------------------------------- launch
extern "C" void kernel_launch(void* const* d_in, const int* in_sizes, int n_in,
                              void* d_out, int out_size) {
    (void)in_sizes; (void)n_in; (void)out_size;
    const float* img = (const float*)d_in[0];
    float* out = (float*)d_out;

    dim3 tg(32, 32, 16);       // 32x32 tiles
    dim3 hg(16, 16);           // 64-row stripes x 16 batches

    k_reset<<<1, 64>>>();
    k_main<<<tg, 256>>>(img);
    k_hi<<<1, 32>>>();
    k_class<<<TOTAL / 256, 256>>>();
    for (int p = 0; p < NPASS; p++) k_hystb<<<hg, 256>>>(p);
    k_final<<<TOTAL / 256, 256>>>(out);
}

// round 5
// speedup vs baseline: 1.8626x; 1.2245x over previous
#include <cuda_runtime.h>
#include <math.h>

// Problem constants
static constexpr int IW = 1024;
static constexpr int IH = 1024;
static constexpr int NB = 16;
static constexpr int IMG = IW * IH;           // 1<<20
static constexpr int TOTAL = NB * IMG;        // 16M
static constexpr int NPASS = 16;
static constexpr int WPR = IW / 32;           // 32 words per row
static constexpr int WPI = IMG / 32;          // words per image

// Scratch (device globals: allocation-free rule)
__device__ float         g_thin[TOTAL];        // 64MB SQUARED thin magnitudes
__device__ unsigned int  g_sbits[TOTAL / 32];  // 2MB strong bitmap
__device__ unsigned int  g_wbits[TOTAL / 32];  // 2MB weak bitmap
__device__ unsigned int  g_magmax[NB];         // per-batch max squared mag, float bits
__device__ unsigned int  g_thinmax[NB];        // per-batch max squared thin, float bits
__device__ float2        g_thr[NB];            // per-batch squared-domain thresholds (hi, lo)
__device__ int           g_flags[NPASS];       // hysteresis per-pass "changed" flags

// ---------------------------------------------------------------- reset
__global__ void k_reset() {
    int t = threadIdx.x;
    if (t < NB) { g_magmax[t] = 0u; g_thinmax[t] = 0u; }
    if (t < NPASS) g_flags[t] = 0;
}

// ---------------------------------------------------------------- fused blur + sobel + NMS (squared domain)
__global__ void __launch_bounds__(256) k_main(const float* __restrict__ img) {
    __shared__ float si[40][40];   // raw img, halo 4
    __shared__ float hb[40][36];   // horizontal blur
    __shared__ float sb[36][36];   // blurred, halo 2 (0 outside image = conv padding)
    __shared__ float sm[34][34];   // SQUARED mag, halo 1 (0 outside image)
    __shared__ float red[16];
    const int b  = blockIdx.z;
    const int x0 = blockIdx.x * 32, y0 = blockIdx.y * 32;
    const float* im = img + (size_t)b * IMG;
    const int tid = threadIdx.x;

    const bool interior = (x0 >= 4) && (x0 + 36 <= IW) && (y0 >= 4) && (y0 + 36 <= IH);
    if (interior) {
        const float* base = im + (y0 - 4) * IW + (x0 - 4);
        for (int i = tid; i < 40 * 40; i += 256) {
            int r = i / 40, c = i % 40;
            si[r][c] = base[r * IW + c];
        }
    } else {
        for (int i = tid; i < 40 * 40; i += 256) {
            int r = i / 40, c = i % 40;
            int gy = y0 + r - 4, gx = x0 + c - 4;
            float v = 0.f;
            if ((unsigned)gy < (unsigned)IH && (unsigned)gx < (unsigned)IW) v = im[gy * IW + gx];
            si[r][c] = v;
        }
    }
    __syncthreads();

    // unnormalized gaussian window, sigma=1, K=5
    const float G0 = 0.13533528323661270231f;  // exp(-2)
    const float G1 = 0.60653065971263342360f;  // exp(-0.5)

    for (int i = tid; i < 40 * 36; i += 256) {
        int r = i / 36, c = i % 36;
        float v = G0 * si[r][c];
        v += G1 * si[r][c + 1];
        v += si[r][c + 2];
        v += G1 * si[r][c + 3];
        v += G0 * si[r][c + 4];
        hb[r][c] = v;
    }
    __syncthreads();

    for (int i = tid; i < 36 * 36; i += 256) {
        int r = i / 36, c = i % 36;
        int gy = y0 + r - 2, gx = x0 + c - 2;
        float v = 0.f;
        if ((unsigned)gy < (unsigned)IH && (unsigned)gx < (unsigned)IW) {
            v = G0 * hb[r][c];
            v += G1 * hb[r + 1][c];
            v += hb[r + 2][c];
            v += G1 * hb[r + 3][c];
            v += G0 * hb[r + 4][c];
        }
        sb[r][c] = v;
    }
    __syncthreads();

    for (int i = tid; i < 34 * 34; i += 256) {
        int r = i / 34, c = i % 34;
        int gy = y0 + r - 1, gx = x0 + c - 1;
        float m = 0.f;
        if ((unsigned)gy < (unsigned)IH && (unsigned)gx < (unsigned)IW) {
            float a0 = sb[r][c],     a1 = sb[r][c + 1],     a2 = sb[r][c + 2];
            float b0 = sb[r + 1][c],                        b2 = sb[r + 1][c + 2];
            float c0 = sb[r + 2][c], c1 = sb[r + 2][c + 1], c2 = sb[r + 2][c + 2];
            float Ix = (a0 - a2) + 2.f * (b0 - b2) + (c0 - c2);
            float Iy = (a0 - c0) + 2.f * (a1 - c1) + (a2 - c2);
            m = Ix * Ix + Iy * Iy;     // squared magnitude (no sqrt)
        }
        sm[r][c] = m;
    }
    __syncthreads();

    const int cx = tid & 31;
    const int r0 = tid >> 5;
    const float T1 = 0.41421356237309503f;   // tan(22.5 deg)
    float mmax = 0.f, tmax = 0.f;
    float* tp = g_thin + (size_t)b * IMG;

    for (int ry = r0; ry < 32; ry += 8) {
        const int r = ry + 1, c = cx + 1;   // sm coords of this pixel
        float m = sm[r][c];
        // recompute gradient at this pixel (sb window offset matches sm coords)
        float a0 = sb[r][c],     a1 = sb[r][c + 1],     a2 = sb[r][c + 2];
        float b0 = sb[r + 1][c],                        b2 = sb[r + 1][c + 2];
        float c0 = sb[r + 2][c], c1 = sb[r + 2][c + 1], c2 = sb[r + 2][c + 2];
        float Ix = (a0 - a2) + 2.f * (b0 - b2) + (c0 - c2);
        float Iy = (a0 - c0) + 2.f * (a1 - c1) + (a2 - c2);
        // Quantized-direction axis without atan2 (only idx mod 4 matters; ties
        // match round-half-even of the reference).
        float ax = fabsf(Ix), ay = fabsf(Iy);
        int dy, dx;
        if (ay <= T1 * ax)      { dy = 0; dx = 1; }                       // E-W
        else if (ax <= T1 * ay) { dy = 1; dx = 0; }                       // N-S
        else if ((__float_as_int(Ix) ^ __float_as_int(Iy)) >= 0) { dy = 1; dx = 1; }  // 45 deg
        else                    { dy = 1; dx = -1; }                      // 135 deg
        float n1 = sm[r + dy][c + dx];
        float n2 = sm[r - dy][c - dx];
        float thin = (m > n1 && m > n2) ? m : 0.f;   // squared-domain strict compares
        tp[(y0 + ry) * IW + x0 + cx] = thin;
        mmax = fmaxf(mmax, m);
        tmax = fmaxf(tmax, thin);
    }

    for (int o = 16; o; o >>= 1) {
        mmax = fmaxf(mmax, __shfl_xor_sync(0xffffffffu, mmax, o));
        tmax = fmaxf(tmax, __shfl_xor_sync(0xffffffffu, tmax, o));
    }
    int warp = tid >> 5, lane = tid & 31;
    if (lane == 0) { red[warp] = mmax; red[warp + 8] = tmax; }
    __syncthreads();
    if (tid == 0) {
        float a = red[0], t2 = red[8];
        for (int w = 1; w < 8; w++) { a = fmaxf(a, red[w]); t2 = fmaxf(t2, red[w + 8]); }
        atomicMax(&g_magmax[b], __float_as_uint(a));
        atomicMax(&g_thinmax[b], __float_as_uint(t2));
    }
}

// ---------------------------------------------------------------- thresholds (exact, squared domain)
// sqrtf is correctly rounded & monotone: max(sqrt(s_i)) == sqrt(max s_i) bit-exact.
// Binary search inverts the EXACT predicate "sqrtf(s)/M >= thr" so k_class's
// compares are boolean-identical to the reference's divide-then-compare.
__global__ void k_hi() {
    __shared__ float s_hi;
    int t = threadIdx.x;
    float M = 1.f, v = 0.f;
    if (t < NB) {
        M = sqrtf(__uint_as_float(g_magmax[t]));
        v = sqrtf(__uint_as_float(g_thinmax[t])) / M;
    }
    float mx = v;
    for (int o = 16; o; o >>= 1) mx = fmaxf(mx, __shfl_xor_sync(0xffffffffu, mx, o));
    if (t == 0) s_hi = mx * 0.15f;
    __syncwarp();
    float hiv = s_hi;
    if (t < NB) {
        // min float s >= 0 with sqrtf(s)/M >= thr (predicate monotone in s-bits)
        unsigned lo, hi_, mid;
        lo = 0u; hi_ = 0x7F800000u;
        while (lo < hi_) {
            mid = (lo + hi_) >> 1;
            if (sqrtf(__uint_as_float(mid)) / M >= hiv) hi_ = mid; else lo = mid + 1u;
        }
        float thrH = __uint_as_float(lo);
        lo = 0u; hi_ = 0x7F800000u;
        while (lo < hi_) {
            mid = (lo + hi_) >> 1;
            if (sqrtf(__uint_as_float(mid)) / M >= 0.00392f) hi_ = mid; else lo = mid + 1u;
        }
        g_thr[t] = make_float2(thrH, __uint_as_float(lo));
    }
}

// ---------------------------------------------------------------- classify -> bitmaps (compare-only, 4 px/thread)
__global__ void __launch_bounds__(256) k_class() {
    const int warpg = blockIdx.x * 8 + (threadIdx.x >> 5);  // global warp id
    const int lane  = threadIdx.x & 31;
    const int base  = warpg * 128;                          // 128 px per warp
    const float2 thr = g_thr[base >> 20];
    unsigned sw[4], ww[4];
#pragma unroll
    for (int k = 0; k < 4; k++) {
        float s = g_thin[base + 32 * k + lane];
        bool st = (s >= thr.x);
        bool wk = !st && (s >= thr.y);
        sw[k] = __ballot_sync(0xffffffffu, st);
        ww[k] = __ballot_sync(0xffffffffu, wk);
    }
    if (lane < 4) {
        g_sbits[(base >> 5) + lane] = sw[lane];
        g_wbits[(base >> 5) + lane] = ww[lane];
    }
}

// ---------------------------------------------------------------- hysteresis pass on bitmaps
__global__ void __launch_bounds__(256) k_hystb(int pass) {
    if (pass > 0 && g_flags[pass - 1] == 0) return;   // converged: cheap no-op pass

    __shared__ unsigned us[66][WPR];
    __shared__ unsigned uw[64][WPR];
    __shared__ int s_changed, s_any;
    const int y0 = blockIdx.x * 64;
    const int b  = blockIdx.y;
    const unsigned* S = g_sbits + b * WPI;
    const unsigned* W = g_wbits + b * WPI;
    const int tid = threadIdx.x;

    if (tid == 0) s_any = 0;
    for (int i = tid; i < 66 * WPR; i += 256) {
        int r = i >> 5, w = i & 31;
        int gy = y0 + r - 1;
        us[r][w] = ((unsigned)gy < (unsigned)IH) ? S[gy * WPR + w] : 0u;
    }
    for (int i = tid; i < 64 * WPR; i += 256) {
        int r = i >> 5, w = i & 31;
        uw[r][w] = W[(y0 + r) * WPR + w];
    }

    for (;;) {
        __syncthreads();
        if (tid == 0) s_changed = 0;
        __syncthreads();
        for (int p = tid; p < 64 * WPR; p += 256) {
            int r = p >> 5, w = p & 31;
            unsigned wk = uw[r][w];
            if (!wk) continue;
            unsigned cen = us[r + 1][w];
            wk &= ~cen;
            if (!wk) continue;
            unsigned up = us[r][w], dn = us[r + 2][w];
            unsigned pu = w ? us[r][w - 1] : 0u,      nu = (w < 31) ? us[r][w + 1] : 0u;
            unsigned pc = w ? us[r + 1][w - 1] : 0u,  nc = (w < 31) ? us[r + 1][w + 1] : 0u;
            unsigned pd = w ? us[r + 2][w - 1] : 0u,  nd = (w < 31) ? us[r + 2][w + 1] : 0u;
            unsigned nb = up | (up << 1) | (up >> 1) | (pu >> 31) | (nu << 31)
                        | dn | (dn << 1) | (dn >> 1) | (pd >> 31) | (nd << 31)
                        |      (cen << 1) | (cen >> 1) | (pc >> 31) | (nc << 31);
            unsigned ns = wk & nb;
            if (ns) { us[r + 1][w] = cen | ns; s_changed = 1; s_any = 1; }
        }
        __syncthreads();
        if (!s_changed) break;
    }

    if (s_any) {
        unsigned* So = g_sbits + b * WPI;
        for (int i = tid; i < 64 * WPR; i += 256) {
            int r = i >> 5, w = i & 31;
            So[(y0 + r) * WPR + w] = us[r + 1][w];
        }
        if (tid == 0) g_flags[pass] = 1;
    }
}

// ---------------------------------------------------------------- final write (4 px/thread, float4)
__global__ void __launch_bounds__(256) k_final(float4* __restrict__ out) {
    int q = blockIdx.x * 256 + threadIdx.x;     // quad index
    int i = q * 4;
    unsigned w = g_sbits[i >> 5];
    unsigned sh = (w >> (i & 31));
    float4 v;
    v.x = (sh & 1u) ? 255.0f : 0.0f;
    v.y = (sh & 2u) ? 255.0f : 0.0f;
    v.z = (sh & 4u) ? 255.0f : 0.0f;
    v.w = (sh & 8u) ? 255.0f : 0.0f;
    out[q] = v;
}

// ---------------------------------------------------------------- launch
extern "C" void kernel_launch(void* const* d_in, const int* in_sizes, int n_in,
                              void* d_out, int out_size) {
    (void)in_sizes; (void)n_in; (void)out_size;
    const float* img = (const float*)d_in[0];

    dim3 tg(32, 32, 16);       // 32x32 tiles
    dim3 hg(16, 16);           // 64-row stripes x 16 batches

    k_reset<<<1, 64>>>();
    k_main<<<tg, 256>>>(img);
    k_hi<<<1, 32>>>();
    k_class<<<TOTAL / (256 * 4), 256>>>();
    for (int p = 0; p < NPASS; p++) k_hystb<<<hg, 256>>>(p);
    k_final<<<TOTAL / 1024, 256>>>((float4*)d_out);
}